// round 2
// baseline (speedup 1.0000x reference)
#include <cuda_runtime.h>

#define DIMD 33
#define H_ORG 2160
#define W_ORG 3840
#define HW (H_ORG * W_ORG)          // 8294400
#define LUTN (DIMD * DIMD * DIMD)   // 35937
#define NPIX 65536                  // 256*256 small image
#define NFEAT 10
#define NBLK_FEAT 256

// ---- device scratch (no allocations allowed) ----
__device__ float  g_partials[NBLK_FEAT * NFEAT];
__device__ float  g_P[3 * 5 * 1089];     // P[ch][s][q]
__device__ float4 g_lut4[LUTN];          // packed (Lr,Lg,Lb,0) per spatial cell

// ============================================================
// Kernel A: gather features, block-reduce partial sums (deterministic)
// ============================================================
__global__ void feat_kernel(const int* __restrict__ msb, const int* __restrict__ lsb,
                            const float* __restrict__ fm, const float* __restrict__ fl) {
    int pid = blockIdx.x * 256 + threadIdx.x;

    int imr = msb[pid], img = msb[pid + NPIX], imb = msb[pid + 2 * NPIX];
    int ilr = lsb[pid], ilg = lsb[pid + NPIX], ilb = lsb[pid + 2 * NPIX];
    int imx = imr * 4096 + img * 256 + imb * 16;
    int ilx = ilr * 4096 + ilg * 256 + ilb * 16;

    float acc[NFEAT];
#pragma unroll
    for (int f = 0; f < NFEAT; f++)
        acc[f] = fm[imx * NFEAT + f] + fl[ilx * NFEAT + f];

    // warp tree reduction (deterministic)
#pragma unroll
    for (int f = 0; f < NFEAT; f++) {
#pragma unroll
        for (int o = 16; o > 0; o >>= 1)
            acc[f] += __shfl_down_sync(0xffffffffu, acc[f], o);
    }

    __shared__ float sw[8][NFEAT];
    int warp = threadIdx.x >> 5, lane = threadIdx.x & 31;
    if (lane == 0) {
#pragma unroll
        for (int f = 0; f < NFEAT; f++) sw[warp][f] = acc[f];
    }
    __syncthreads();
    if (threadIdx.x == 0) {
#pragma unroll
        for (int f = 0; f < NFEAT; f++) {
            float s = 0.f;
#pragma unroll
            for (int w = 0; w < 8; w++) s += sw[w][f];
            g_partials[blockIdx.x * NFEAT + f] = s;
        }
    }
}

// ============================================================
// Kernel B: pooled -> weights -> collapsed LUT synthesis
// d3lut_r[b,g,r] = sum_s s_layers[r,s] * P0[s, b*33+g]
// d3lut_g[b,g,r] = sum_s s_layers[g,s] * P1[s, b*33+r]
// d3lut_b[b,g,r] = sum_s s_layers[b,s] * P2[s, g*33+r]
// P[ch][s,q] = sum_w Q[ch][s,w] * w_layers[w,q]
// Q[ch][s,w] = sum_n wt[n] * luts[(s*30+3n+ch)*10 + w]
// ============================================================
__global__ void lut_build_kernel(const float* __restrict__ lut_cat,
                                 const float* __restrict__ s_layers,
                                 const float* __restrict__ w_layers,
                                 const float* __restrict__ luts,
                                 float* __restrict__ out_lut) {
    __shared__ float s_pooled[NFEAT];
    __shared__ float s_wt[NFEAT];
    __shared__ float s_Q[150];       // [ch*5+s]*10 + w
    __shared__ float s_sl[DIMD * 5];
    int t = threadIdx.x;

    if (t < NFEAT) {
        float s = 0.f;
        for (int b = 0; b < NBLK_FEAT; b++) s += g_partials[b * NFEAT + t];
        s_pooled[t] = s * (1.0f / (float)NPIX);
    }
    if (t < DIMD * 5) s_sl[t] = s_layers[t];
    __syncthreads();

    if (t == 0) {
        int mid[NFEAT];
#pragma unroll
        for (int f = 0; f < NFEAT; f++) {
            float p = rintf(s_pooled[f] * 2.0f) * 0.5f;   // round half-even like jnp.round
            p = fminf(fmaxf(p, -16.0f), 15.5f);
            mid[f] = (int)(p * 2.0f) + 32;
        }
#pragma unroll
        for (int n = 0; n < NFEAT; n++) {
            float w = 0.f;
#pragma unroll
            for (int i = 0; i < 5; i++) {
                int index = mid[2 * i] * 64 + mid[2 * i + 1];
                w += (lut_cat[(i * 4096 + index) * NFEAT + n] - 32.0f) * 0.25f;
            }
            s_wt[n] = w;
        }
    }
    __syncthreads();

    if (t < 150) {
        int ch = t / 50, s = (t / 10) % 5, w = t % 10;
        float q = 0.f;
#pragma unroll
        for (int n = 0; n < NFEAT; n++)
            q += s_wt[n] * luts[(s * 30 + 3 * n + ch) * NFEAT + w];
        s_Q[t] = q;   // == s_Q[(ch*5+s)*10 + w]
    }
    __syncthreads();

    for (int idx = t; idx < 3 * 5 * 1089; idx += blockDim.x) {
        int chs = idx / 1089;   // ch*5+s
        int q   = idx % 1089;
        float p = 0.f;
#pragma unroll
        for (int w = 0; w < 10; w++)
            p += s_Q[chs * 10 + w] * w_layers[w * 1089 + q];
        g_P[idx] = p;
    }
    __syncthreads();

    for (int v = t; v < LUTN; v += blockDim.x) {
        int b = v / 1089;
        int g = (v / 33) % 33;
        int r = v % 33;
        int qr = b * 33 + g, qg = b * 33 + r, qb = g * 33 + r;
        float Lr = 0.f, Lg = 0.f, Lb = 0.f;
#pragma unroll
        for (int s = 0; s < 5; s++) {
            Lr += s_sl[r * 5 + s] * g_P[(0 * 5 + s) * 1089 + qr];
            Lg += s_sl[g * 5 + s] * g_P[(1 * 5 + s) * 1089 + qg];
            Lb += s_sl[b * 5 + s] * g_P[(2 * 5 + s) * 1089 + qb];
        }
        g_lut4[v] = make_float4(Lr, Lg, Lb, 0.f);
        out_lut[v]            = Lr;
        out_lut[LUTN + v]     = Lg;
        out_lut[2 * LUTN + v] = Lb;
    }
}

// ============================================================
// Kernel C: trilinear apply over 2160x3840x3, float4-vectorized
// ============================================================
__global__ void __launch_bounds__(256) apply_kernel(const float* __restrict__ img,
                                                    float* __restrict__ out) {
    int i = blockIdx.x * blockDim.x + threadIdx.x;   // float4 pixel-group index
    if (i >= HW / 4) return;

    const float4* R = (const float4*)(img);
    const float4* G = (const float4*)(img + HW);
    const float4* B = (const float4*)(img + 2 * HW);
    float4 r4 = R[i], g4 = G[i], b4 = B[i];

    const float binsize = (float)(1.000001 / (DIMD - 1));

    float rr[4] = {r4.x, r4.y, r4.z, r4.w};
    float gg[4] = {g4.x, g4.y, g4.z, g4.w};
    float bb[4] = {b4.x, b4.y, b4.z, b4.w};
    float ro[4], go[4], bo[4];

#pragma unroll
    for (int k = 0; k < 4; k++) {
        float rf = rr[k] / binsize;
        float gf = gg[k] / binsize;
        float bf = bb[k] / binsize;
        float rfl = floorf(rf), gfl = floorf(gf), bfl = floorf(bf);
        int rid = min(max((int)rfl, 0), DIMD - 2);
        int gid = min(max((int)gfl, 0), DIMD - 2);
        int bid = min(max((int)bfl, 0), DIMD - 2);
        float rd = rf - rfl, gd = gf - gfl, bd = bf - bfl;
        float r0 = 1.0f - rd, g0 = 1.0f - gd, b0 = 1.0f - bd;

        int base = (bid * 33 + gid) * 33 + rid;
        float4 c000 = __ldg(&g_lut4[base]);
        float4 c001 = __ldg(&g_lut4[base + 1]);
        float4 c010 = __ldg(&g_lut4[base + 33]);
        float4 c011 = __ldg(&g_lut4[base + 34]);
        float4 c100 = __ldg(&g_lut4[base + 1089]);
        float4 c101 = __ldg(&g_lut4[base + 1090]);
        float4 c110 = __ldg(&g_lut4[base + 1122]);
        float4 c111 = __ldg(&g_lut4[base + 1123]);

        float w000 = r0 * g0 * b0, w001 = rd * g0 * b0;
        float w010 = r0 * gd * b0, w011 = rd * gd * b0;
        float w100 = r0 * g0 * bd, w101 = rd * g0 * bd;
        float w110 = r0 * gd * bd, w111 = rd * gd * bd;

        float sr = w000 * c000.x + w001 * c001.x + w010 * c010.x + w011 * c011.x
                 + w100 * c100.x + w101 * c101.x + w110 * c110.x + w111 * c111.x;
        float sg = w000 * c000.y + w001 * c001.y + w010 * c010.y + w011 * c011.y
                 + w100 * c100.y + w101 * c101.y + w110 * c110.y + w111 * c111.y;
        float sb = w000 * c000.z + w001 * c001.z + w010 * c010.z + w011 * c011.z
                 + w100 * c100.z + w101 * c101.z + w110 * c110.z + w111 * c111.z;

        ro[k] = sr + rr[k];
        go[k] = sg + gg[k];
        bo[k] = sb + bb[k];
    }

    float4* OR = (float4*)(out);
    float4* OG = (float4*)(out + HW);
    float4* OB = (float4*)(out + 2 * HW);
    OR[i] = make_float4(ro[0], ro[1], ro[2], ro[3]);
    OG[i] = make_float4(go[0], go[1], go[2], go[3]);
    OB[i] = make_float4(bo[0], bo[1], bo[2], bo[3]);
}

// ============================================================
extern "C" void kernel_launch(void* const* d_in, const int* in_sizes, int n_in,
                              void* d_out, int out_size) {
    const int*   msb      = (const int*)d_in[0];
    const int*   lsb      = (const int*)d_in[1];
    const float* img      = (const float*)d_in[2];
    const float* fm       = (const float*)d_in[3];
    const float* fl       = (const float*)d_in[4];
    const float* lut_cat  = (const float*)d_in[5];
    const float* s_layers = (const float*)d_in[6];
    const float* w_layers = (const float*)d_in[7];
    const float* luts     = (const float*)d_in[8];
    float* out = (float*)d_out;

    feat_kernel<<<NBLK_FEAT, 256>>>(msb, lsb, fm, fl);
    lut_build_kernel<<<1, 1024>>>(lut_cat, s_layers, w_layers, luts, out + 3 * HW);

    int n4 = HW / 4;                       // 2073600
    int blocks = (n4 + 255) / 256;         // 8100
    apply_kernel<<<blocks, 256>>>(img, out);
}

// round 4
// speedup vs baseline: 1.3738x; 1.3738x over previous
#include <cuda_runtime.h>
#include <cuda_fp16.h>

#define DIMD 33
#define H_ORG 2160
#define W_ORG 3840
#define HW (H_ORG * W_ORG)          // 8294400
#define LUTN (DIMD * DIMD * DIMD)   // 35937
#define NPIX 65536                  // 256*256 small image
#define NFEAT 10
#define NBLK_FEAT 256

// ---- device scratch (no allocations allowed) ----
__device__ float  g_partials[NBLK_FEAT * NFEAT];
__device__ float  g_P[3 * 5 * 1089];     // P[ch][s][q]
__device__ float4 g_lut4[LUTN];          // fp32 packed (Lr,Lg,Lb,0)
__device__ uint4  g_lutH[LUTN];          // fp16 packed {Lr0,Lg0,Lb0,Lr1,Lg1,Lb1,0,0}

// ============================================================
// Kernel A: gather features, block-reduce partial sums (deterministic)
// ============================================================
__global__ void feat_kernel(const int* __restrict__ msb, const int* __restrict__ lsb,
                            const float* __restrict__ fm, const float* __restrict__ fl) {
    int pid = blockIdx.x * 256 + threadIdx.x;

    int imr = msb[pid], img = msb[pid + NPIX], imb = msb[pid + 2 * NPIX];
    int ilr = lsb[pid], ilg = lsb[pid + NPIX], ilb = lsb[pid + 2 * NPIX];
    long imx = (long)(imr * 4096 + img * 256 + imb * 16) * NFEAT;
    long ilx = (long)(ilr * 4096 + ilg * 256 + ilb * 16) * NFEAT;

    float acc[NFEAT];
    // rows are 40B, 8B-aligned -> 5 x float2 per row
    const float2* fm2 = (const float2*)(fm + imx);
    const float2* fl2 = (const float2*)(fl + ilx);
#pragma unroll
    for (int f = 0; f < 5; f++) {
        float2 a = __ldg(&fm2[f]);
        float2 b = __ldg(&fl2[f]);
        acc[2 * f]     = a.x + b.x;
        acc[2 * f + 1] = a.y + b.y;
    }

    // warp tree reduction (deterministic)
#pragma unroll
    for (int f = 0; f < NFEAT; f++) {
#pragma unroll
        for (int o = 16; o > 0; o >>= 1)
            acc[f] += __shfl_down_sync(0xffffffffu, acc[f], o);
    }

    __shared__ float sw[8][NFEAT];
    int warp = threadIdx.x >> 5, lane = threadIdx.x & 31;
    if (lane == 0) {
#pragma unroll
        for (int f = 0; f < NFEAT; f++) sw[warp][f] = acc[f];
    }
    __syncthreads();
    if (threadIdx.x == 0) {
#pragma unroll
        for (int f = 0; f < NFEAT; f++) {
            float s = 0.f;
#pragma unroll
            for (int w = 0; w < 8; w++) s += sw[w][f];
            g_partials[blockIdx.x * NFEAT + f] = s;
        }
    }
}

// ============================================================
// Kernel B: pooled -> weights -> collapsed LUT synthesis (fp32)
// ============================================================
__global__ void lut_build_kernel(const float* __restrict__ lut_cat,
                                 const float* __restrict__ s_layers,
                                 const float* __restrict__ w_layers,
                                 const float* __restrict__ luts,
                                 float* __restrict__ out_lut) {
    __shared__ float s_pooled[NFEAT];
    __shared__ float s_wt[NFEAT];
    __shared__ float s_Q[150];       // [ch*5+s]*10 + w
    __shared__ float s_sl[DIMD * 5];
    int t = threadIdx.x;

    if (t < NFEAT) {
        float s = 0.f;
        for (int b = 0; b < NBLK_FEAT; b++) s += g_partials[b * NFEAT + t];
        s_pooled[t] = s * (1.0f / (float)NPIX);
    }
    if (t < DIMD * 5) s_sl[t] = s_layers[t];
    __syncthreads();

    if (t == 0) {
        int mid[NFEAT];
#pragma unroll
        for (int f = 0; f < NFEAT; f++) {
            float p = rintf(s_pooled[f] * 2.0f) * 0.5f;   // round half-even like jnp.round
            p = fminf(fmaxf(p, -16.0f), 15.5f);
            mid[f] = (int)(p * 2.0f) + 32;
        }
#pragma unroll
        for (int n = 0; n < NFEAT; n++) {
            float w = 0.f;
#pragma unroll
            for (int i = 0; i < 5; i++) {
                int index = mid[2 * i] * 64 + mid[2 * i + 1];
                w += (lut_cat[(i * 4096 + index) * NFEAT + n] - 32.0f) * 0.25f;
            }
            s_wt[n] = w;
        }
    }
    __syncthreads();

    if (t < 150) {
        int ch = t / 50, s = (t / 10) % 5, w = t % 10;
        float q = 0.f;
#pragma unroll
        for (int n = 0; n < NFEAT; n++)
            q += s_wt[n] * luts[(s * 30 + 3 * n + ch) * NFEAT + w];
        s_Q[t] = q;
    }
    __syncthreads();

    for (int idx = t; idx < 3 * 5 * 1089; idx += blockDim.x) {
        int chs = idx / 1089;   // ch*5+s
        int q   = idx % 1089;
        float p = 0.f;
#pragma unroll
        for (int w = 0; w < 10; w++)
            p += s_Q[chs * 10 + w] * w_layers[w * 1089 + q];
        g_P[idx] = p;
    }
    __syncthreads();

    for (int v = t; v < LUTN; v += blockDim.x) {
        int b = v / 1089;
        int g = (v / 33) % 33;
        int r = v % 33;
        int qr = b * 33 + g, qg = b * 33 + r, qb = g * 33 + r;
        float Lr = 0.f, Lg = 0.f, Lb = 0.f;
#pragma unroll
        for (int s = 0; s < 5; s++) {
            Lr += s_sl[r * 5 + s] * g_P[(0 * 5 + s) * 1089 + qr];
            Lg += s_sl[g * 5 + s] * g_P[(1 * 5 + s) * 1089 + qg];
            Lb += s_sl[b * 5 + s] * g_P[(2 * 5 + s) * 1089 + qb];
        }
        g_lut4[v] = make_float4(Lr, Lg, Lb, 0.f);
        out_lut[v]            = Lr;
        out_lut[LUTN + v]     = Lg;
        out_lut[2 * LUTN + v] = Lb;
    }
}

// ============================================================
// Kernel B2: pack fp32 LUT into fp16 r-pair entries (16B each)
// entry[v] = {Lr(v), Lg(v), Lb(v), Lr(v+1), Lg(v+1), Lb(v+1), 0, 0}
// ============================================================
__global__ void pack_kernel() {
    int v = blockIdx.x * blockDim.x + threadIdx.x;
    if (v >= LUTN) return;
    int r = v % DIMD;
    float4 c0 = g_lut4[v];
    float4 c1 = (r < DIMD - 1) ? g_lut4[v + 1] : c0;
    union { __half h[8]; uint4 u; } e;
    e.h[0] = __float2half_rn(c0.x);
    e.h[1] = __float2half_rn(c0.y);
    e.h[2] = __float2half_rn(c0.z);
    e.h[3] = __float2half_rn(c1.x);
    e.h[4] = __float2half_rn(c1.y);
    e.h[5] = __float2half_rn(c1.z);
    e.h[6] = __ushort_as_half((unsigned short)0);
    e.h[7] = __ushort_as_half((unsigned short)0);
    g_lutH[v] = e.u;
}

// ============================================================
// Kernel C: trilinear apply, 4 gathers/pixel (fp16 packed r-pairs)
// ============================================================
__global__ void __launch_bounds__(256) apply_kernel(const float* __restrict__ img,
                                                    float* __restrict__ out) {
    int i = blockIdx.x * blockDim.x + threadIdx.x;   // float4 pixel-group index
    if (i >= HW / 4) return;

    const float4* R = (const float4*)(img);
    const float4* G = (const float4*)(img + HW);
    const float4* B = (const float4*)(img + 2 * HW);
    float4 r4 = R[i], g4 = G[i], b4 = B[i];

    const float inv_binsize = (float)((DIMD - 1) / 1.000001);

    float rr[4] = {r4.x, r4.y, r4.z, r4.w};
    float gg[4] = {g4.x, g4.y, g4.z, g4.w};
    float bb[4] = {b4.x, b4.y, b4.z, b4.w};
    float ro[4], go[4], bo[4];

#pragma unroll
    for (int k = 0; k < 4; k++) {
        float rf = rr[k] * inv_binsize;
        float gf = gg[k] * inv_binsize;
        float bf = bb[k] * inv_binsize;
        float rfl = floorf(rf), gfl = floorf(gf), bfl = floorf(bf);
        int rid = min(max((int)rfl, 0), DIMD - 2);
        int gid = min(max((int)gfl, 0), DIMD - 2);
        int bid = min(max((int)bfl, 0), DIMD - 2);
        float rd = rf - rfl, gd = gf - gfl, bd = bf - bfl;

        int base = (bid * 33 + gid) * 33 + rid;
        uint4 q00 = __ldg(&g_lutH[base]);
        uint4 q01 = __ldg(&g_lutH[base + 33]);
        uint4 q10 = __ldg(&g_lutH[base + 1089]);
        uint4 q11 = __ldg(&g_lutH[base + 1122]);

        // decode + lerp along r:  c = v0 + rd*(v1 - v0)
        float cr00, cg00, cb00, cr01, cg01, cb01, cr10, cg10, cb10, cr11, cg11, cb11;
        {
            float2 p0 = __half22float2(*(__half2*)&q00.x);  // Lr0, Lg0
            float2 p1 = __half22float2(*(__half2*)&q00.y);  // Lb0, Lr1
            float2 p2 = __half22float2(*(__half2*)&q00.z);  // Lg1, Lb1
            cr00 = fmaf(rd, p1.y - p0.x, p0.x);
            cg00 = fmaf(rd, p2.x - p0.y, p0.y);
            cb00 = fmaf(rd, p2.y - p1.x, p1.x);
        }
        {
            float2 p0 = __half22float2(*(__half2*)&q01.x);
            float2 p1 = __half22float2(*(__half2*)&q01.y);
            float2 p2 = __half22float2(*(__half2*)&q01.z);
            cr01 = fmaf(rd, p1.y - p0.x, p0.x);
            cg01 = fmaf(rd, p2.x - p0.y, p0.y);
            cb01 = fmaf(rd, p2.y - p1.x, p1.x);
        }
        {
            float2 p0 = __half22float2(*(__half2*)&q10.x);
            float2 p1 = __half22float2(*(__half2*)&q10.y);
            float2 p2 = __half22float2(*(__half2*)&q10.z);
            cr10 = fmaf(rd, p1.y - p0.x, p0.x);
            cg10 = fmaf(rd, p2.x - p0.y, p0.y);
            cb10 = fmaf(rd, p2.y - p1.x, p1.x);
        }
        {
            float2 p0 = __half22float2(*(__half2*)&q11.x);
            float2 p1 = __half22float2(*(__half2*)&q11.y);
            float2 p2 = __half22float2(*(__half2*)&q11.z);
            cr11 = fmaf(rd, p1.y - p0.x, p0.x);
            cg11 = fmaf(rd, p2.x - p0.y, p0.y);
            cb11 = fmaf(rd, p2.y - p1.x, p1.x);
        }

        // bilinear over (g,b)
        float cr0 = fmaf(gd, cr01 - cr00, cr00);
        float cg0 = fmaf(gd, cg01 - cg00, cg00);
        float cb0 = fmaf(gd, cb01 - cb00, cb00);
        float cr1 = fmaf(gd, cr11 - cr10, cr10);
        float cg1 = fmaf(gd, cg11 - cg10, cg10);
        float cb1 = fmaf(gd, cb11 - cb10, cb10);

        ro[k] = fmaf(bd, cr1 - cr0, cr0) + rr[k];
        go[k] = fmaf(bd, cg1 - cg0, cg0) + gg[k];
        bo[k] = fmaf(bd, cb1 - cb0, cb0) + bb[k];
    }

    float4* OR = (float4*)(out);
    float4* OG = (float4*)(out + HW);
    float4* OB = (float4*)(out + 2 * HW);
    OR[i] = make_float4(ro[0], ro[1], ro[2], ro[3]);
    OG[i] = make_float4(go[0], go[1], go[2], go[3]);
    OB[i] = make_float4(bo[0], bo[1], bo[2], bo[3]);
}

// ============================================================
extern "C" void kernel_launch(void* const* d_in, const int* in_sizes, int n_in,
                              void* d_out, int out_size) {
    const int*   msb      = (const int*)d_in[0];
    const int*   lsb      = (const int*)d_in[1];
    const float* img      = (const float*)d_in[2];
    const float* fm       = (const float*)d_in[3];
    const float* fl       = (const float*)d_in[4];
    const float* lut_cat  = (const float*)d_in[5];
    const float* s_layers = (const float*)d_in[6];
    const float* w_layers = (const float*)d_in[7];
    const float* luts     = (const float*)d_in[8];
    float* out = (float*)d_out;

    feat_kernel<<<NBLK_FEAT, 256>>>(msb, lsb, fm, fl);
    lut_build_kernel<<<1, 1024>>>(lut_cat, s_layers, w_layers, luts, out + 3 * HW);
    pack_kernel<<<(LUTN + 255) / 256, 256>>>();

    int n4 = HW / 4;                       // 2073600
    int blocks = (n4 + 255) / 256;         // 8100
    apply_kernel<<<blocks, 256>>>(img, out);
}

// round 6
// speedup vs baseline: 2.4793x; 1.8047x over previous
#include <cuda_runtime.h>
#include <cuda_fp16.h>

#define DIMD 33
#define H_ORG 2160
#define W_ORG 3840
#define HW (H_ORG * W_ORG)          // 8294400
#define LUTN (DIMD * DIMD * DIMD)   // 35937
#define NPIX 65536                  // 256*256 small image
#define NFEAT 10
#define NBLK_FEAT 256

// ---- device scratch (no allocations allowed) ----
__device__ float  g_partials[NBLK_FEAT * NFEAT];
__device__ float  g_Q[150];              // [ch*5+s]*10 + w
__device__ float  g_P[3 * 5 * 1089];     // P[ch][s][q]
__device__ float4 g_lut4[LUTN];          // fp32 packed (Lr,Lg,Lb,0)
__device__ uint4  g_lutPK[LUTN];         // int8 block-scaled {12 vals, fp32 scale}

// ============================================================
// Kernel A: gather features, block-reduce partial sums (deterministic)
// ============================================================
__global__ void feat_kernel(const int* __restrict__ msb, const int* __restrict__ lsb,
                            const float* __restrict__ fm, const float* __restrict__ fl) {
    int pid = blockIdx.x * 256 + threadIdx.x;

    int imr = msb[pid], img = msb[pid + NPIX], imb = msb[pid + 2 * NPIX];
    int ilr = lsb[pid], ilg = lsb[pid + NPIX], ilb = lsb[pid + 2 * NPIX];
    long imx = (long)(imr * 4096 + img * 256 + imb * 16) * NFEAT;
    long ilx = (long)(ilr * 4096 + ilg * 256 + ilb * 16) * NFEAT;

    // rows are 40B at 640B alignment -> float4 x2 + float2
    const float4* fm4 = (const float4*)(fm + imx);
    const float4* fl4 = (const float4*)(fl + ilx);
    float4 a0 = __ldg(&fm4[0]), a1 = __ldg(&fm4[1]);
    float2 a2 = __ldg((const float2*)(fm + imx + 8));
    float4 b0 = __ldg(&fl4[0]), b1 = __ldg(&fl4[1]);
    float2 b2 = __ldg((const float2*)(fl + ilx + 8));

    float acc[NFEAT];
    acc[0] = a0.x + b0.x; acc[1] = a0.y + b0.y;
    acc[2] = a0.z + b0.z; acc[3] = a0.w + b0.w;
    acc[4] = a1.x + b1.x; acc[5] = a1.y + b1.y;
    acc[6] = a1.z + b1.z; acc[7] = a1.w + b1.w;
    acc[8] = a2.x + b2.x; acc[9] = a2.y + b2.y;

#pragma unroll
    for (int f = 0; f < NFEAT; f++) {
#pragma unroll
        for (int o = 16; o > 0; o >>= 1)
            acc[f] += __shfl_down_sync(0xffffffffu, acc[f], o);
    }

    __shared__ float sw[8][NFEAT];
    int warp = threadIdx.x >> 5, lane = threadIdx.x & 31;
    if (lane == 0) {
#pragma unroll
        for (int f = 0; f < NFEAT; f++) sw[warp][f] = acc[f];
    }
    __syncthreads();
    if (threadIdx.x == 0) {
#pragma unroll
        for (int f = 0; f < NFEAT; f++) {
            float s = 0.f;
#pragma unroll
            for (int w = 0; w < 8; w++) s += sw[w][f];
            g_partials[blockIdx.x * NFEAT + f] = s;
        }
    }
}

// ============================================================
// Kernel B1: pooled -> mid -> weights -> Q (single small block)
// ============================================================
__global__ void bweights_kernel(const float* __restrict__ lut_cat,
                                const float* __restrict__ luts) {
    __shared__ int   smid[NFEAT];
    __shared__ float swt[NFEAT];
    int t = threadIdx.x;

    if (t < NFEAT) {
        float s = 0.f;
        for (int b = 0; b < NBLK_FEAT; b++) s += g_partials[b * NFEAT + t];
        float pooled = s * (1.0f / (float)NPIX);
        float p = rintf(pooled * 2.0f) * 0.5f;      // round half-even like jnp.round
        p = fminf(fmaxf(p, -16.0f), 15.5f);
        smid[t] = (int)(p * 2.0f) + 32;
    }
    __syncthreads();
    if (t < NFEAT) {
        float w = 0.f;
#pragma unroll
        for (int i = 0; i < 5; i++) {
            int index = smid[2 * i] * 64 + smid[2 * i + 1];
            w += (lut_cat[(i * 4096 + index) * NFEAT + t] - 32.0f) * 0.25f;
        }
        swt[t] = w;
    }
    __syncthreads();
    if (t < 150) {
        int ch = t / 50, s = (t / 10) % 5, w = t % 10;
        float q = 0.f;
#pragma unroll
        for (int n = 0; n < NFEAT; n++)
            q += swt[n] * luts[(s * 30 + 3 * n + ch) * NFEAT + w];
        g_Q[t] = q;
    }
}

// ============================================================
// Kernel B2: P[chs][q] = sum_w Q[chs][w] * w_layers[w][q]
// ============================================================
__global__ void p_kernel(const float* __restrict__ w_layers) {
    int idx = blockIdx.x * 256 + threadIdx.x;
    if (idx >= 3 * 5 * 1089) return;
    int chs = idx / 1089;
    int q   = idx % 1089;
    float p = 0.f;
#pragma unroll
    for (int w = 0; w < 10; w++)
        p += g_Q[chs * 10 + w] * __ldg(&w_layers[w * 1089 + q]);
    g_P[idx] = p;
}

// ============================================================
// Kernel B3: final fp32 LUT (+ write d3lut output)
// ============================================================
__global__ void lut_final_kernel(const float* __restrict__ s_layers,
                                 float* __restrict__ out_lut) {
    __shared__ float s_sl[DIMD * 5];
    if (threadIdx.x < DIMD * 5) s_sl[threadIdx.x] = s_layers[threadIdx.x];
    __syncthreads();

    int v = blockIdx.x * 256 + threadIdx.x;
    if (v >= LUTN) return;
    int b = v / 1089;
    int g = (v / 33) % 33;
    int r = v % 33;
    int qr = b * 33 + g, qg = b * 33 + r, qb = g * 33 + r;
    float Lr = 0.f, Lg = 0.f, Lb = 0.f;
#pragma unroll
    for (int s = 0; s < 5; s++) {
        Lr += s_sl[r * 5 + s] * g_P[(0 * 5 + s) * 1089 + qr];
        Lg += s_sl[g * 5 + s] * g_P[(1 * 5 + s) * 1089 + qg];
        Lb += s_sl[b * 5 + s] * g_P[(2 * 5 + s) * 1089 + qb];
    }
    g_lut4[v] = make_float4(Lr, Lg, Lb, 0.f);
    out_lut[v]            = Lr;
    out_lut[LUTN + v]     = Lg;
    out_lut[2 * LUTN + v] = Lb;
}

// ============================================================
// Kernel B4: pack int8 block-scaled entries
// entry[v=(b,g,r)] covers (r..r+1, g..g+1) x 3ch of plane b.
// bytes[ch*4 + gpar*2 + rpar] = round(val/scale)+128 ; word3 = fp32 scale
// ============================================================
__global__ void pack_kernel() {
    int v = blockIdx.x * blockDim.x + threadIdx.x;
    if (v >= LUTN) return;
    int r = v % 33, g = (v / 33) % 33;
    float4 c00 = g_lut4[v];
    float4 c01 = (r < 32) ? g_lut4[v + 1] : c00;
    float4 c10 = (g < 32) ? g_lut4[v + 33] : c00;
    float4 c11 = (g < 32 && r < 32) ? g_lut4[v + 34] : c00;

    float vals[12] = { c00.x, c01.x, c10.x, c11.x,
                       c00.y, c01.y, c10.y, c11.y,
                       c00.z, c01.z, c10.z, c11.z };
    float mx = 1e-30f;
#pragma unroll
    for (int i = 0; i < 12; i++) mx = fmaxf(mx, fabsf(vals[i]));
    float scale = mx * (1.0f / 127.0f);
    float inv   = 127.0f / mx;

    unsigned m[12];
#pragma unroll
    for (int i = 0; i < 12; i++)
        m[i] = (unsigned)((int)rintf(vals[i] * inv) + 128);

    uint4 e;
    e.x = m[0] | (m[1] << 8) | (m[2] << 16) | (m[3] << 24);
    e.y = m[4] | (m[5] << 8) | (m[6] << 16) | (m[7] << 24);
    e.z = m[8] | (m[9] << 8) | (m[10] << 16) | (m[11] << 24);
    e.w = __float_as_uint(scale);
    g_lutPK[v] = e;
}

// ============================================================
// Kernel C: trilinear apply, 2 gathers/pixel (int8 block-scaled)
// ============================================================
__global__ void __launch_bounds__(256) apply_kernel(const float* __restrict__ img,
                                                    float* __restrict__ out) {
    int i = blockIdx.x * blockDim.x + threadIdx.x;   // float4 pixel-group index
    if (i >= HW / 4) return;

    const float4* R = (const float4*)(img);
    const float4* G = (const float4*)(img + HW);
    const float4* B = (const float4*)(img + 2 * HW);
    float4 r4 = R[i], g4 = G[i], b4 = B[i];

    const float inv_binsize = (float)((DIMD - 1) / 1.000001);

    float rr[4] = {r4.x, r4.y, r4.z, r4.w};
    float gg[4] = {g4.x, g4.y, g4.z, g4.w};
    float bb[4] = {b4.x, b4.y, b4.z, b4.w};
    float ro[4], go[4], bo[4];

#pragma unroll
    for (int k = 0; k < 4; k++) {
        float rf = rr[k] * inv_binsize;
        float gf = gg[k] * inv_binsize;
        float bf = bb[k] * inv_binsize;
        float rfl = floorf(rf), gfl = floorf(gf), bfl = floorf(bf);
        int rid = min(max((int)rfl, 0), DIMD - 2);
        int gid = min(max((int)gfl, 0), DIMD - 2);
        int bid = min(max((int)bfl, 0), DIMD - 2);
        float rd = rf - rfl, gd = gf - gfl, bd = bf - bfl;

        int base = (bid * 33 + gid) * 33 + rid;
        uint4 qa = __ldg(&g_lutPK[base]);           // plane bid
        uint4 qb = __ldg(&g_lutPK[base + 1089]);    // plane bid+1

        float r1g0 = rd * (1.0f - gd);              // rd(1-gd)
        float r0g0 = (1.0f - gd) - r1g0;            // (1-rd)(1-gd)  [FIXED]
        float r1g1 = rd * gd;                       // rd*gd
        float r0g1 = gd - r1g1;                     // (1-rd)*gd

        // decode one plane: 3 channels, each word = {m00,m01,m10,m11}
        // half trick: prmt -> 0x6400|m = (1024+m) exact
        float p0r, p0g, p0b, p1r, p1g, p1b;
        {
            float s = __uint_as_float(qa.w);
            float off = -1152.0f * s;               // removes (1024 + 128) bias
#pragma unroll
            for (int c = 0; c < 3; c++) {
                unsigned wv = (c == 0) ? qa.x : (c == 1) ? qa.y : qa.z;
                unsigned h01 = __byte_perm(wv, 0x64646464u, 0x4140);
                unsigned h23 = __byte_perm(wv, 0x64646464u, 0x4342);
                float2 f01 = __half22float2(*(__half2*)&h01);   // 1024+m00, 1024+m01
                float2 f23 = __half22float2(*(__half2*)&h23);   // 1024+m10, 1024+m11
                float acc = r0g0 * f01.x + r1g0 * f01.y + r0g1 * f23.x + r1g1 * f23.y;
                float val = fmaf(acc, s, off);
                if (c == 0) p0r = val; else if (c == 1) p0g = val; else p0b = val;
            }
        }
        {
            float s = __uint_as_float(qb.w);
            float off = -1152.0f * s;
#pragma unroll
            for (int c = 0; c < 3; c++) {
                unsigned wv = (c == 0) ? qb.x : (c == 1) ? qb.y : qb.z;
                unsigned h01 = __byte_perm(wv, 0x64646464u, 0x4140);
                unsigned h23 = __byte_perm(wv, 0x64646464u, 0x4342);
                float2 f01 = __half22float2(*(__half2*)&h01);
                float2 f23 = __half22float2(*(__half2*)&h23);
                float acc = r0g0 * f01.x + r1g0 * f01.y + r0g1 * f23.x + r1g1 * f23.y;
                float val = fmaf(acc, s, off);
                if (c == 0) p1r = val; else if (c == 1) p1g = val; else p1b = val;
            }
        }

        ro[k] = fmaf(bd, p1r - p0r, p0r) + rr[k];
        go[k] = fmaf(bd, p1g - p0g, p0g) + gg[k];
        bo[k] = fmaf(bd, p1b - p0b, p0b) + bb[k];
    }

    float4* OR = (float4*)(out);
    float4* OG = (float4*)(out + HW);
    float4* OB = (float4*)(out + 2 * HW);
    OR[i] = make_float4(ro[0], ro[1], ro[2], ro[3]);
    OG[i] = make_float4(go[0], go[1], go[2], go[3]);
    OB[i] = make_float4(bo[0], bo[1], bo[2], bo[3]);
}

// ============================================================
extern "C" void kernel_launch(void* const* d_in, const int* in_sizes, int n_in,
                              void* d_out, int out_size) {
    const int*   msb      = (const int*)d_in[0];
    const int*   lsb      = (const int*)d_in[1];
    const float* img      = (const float*)d_in[2];
    const float* fm       = (const float*)d_in[3];
    const float* fl       = (const float*)d_in[4];
    const float* lut_cat  = (const float*)d_in[5];
    const float* s_layers = (const float*)d_in[6];
    const float* w_layers = (const float*)d_in[7];
    const float* luts     = (const float*)d_in[8];
    float* out = (float*)d_out;

    feat_kernel<<<NBLK_FEAT, 256>>>(msb, lsb, fm, fl);
    bweights_kernel<<<1, 160>>>(lut_cat, luts);
    p_kernel<<<(3 * 5 * 1089 + 255) / 256, 256>>>(w_layers);
    lut_final_kernel<<<(LUTN + 255) / 256, 256>>>(s_layers, out + 3 * HW);
    pack_kernel<<<(LUTN + 255) / 256, 256>>>();

    int n4 = HW / 4;                       // 2073600
    int blocks = (n4 + 255) / 256;         // 8100
    apply_kernel<<<blocks, 256>>>(img, out);
}

// round 7
// speedup vs baseline: 3.7566x; 1.5152x over previous
#include <cuda_runtime.h>
#include <cuda_fp16.h>

#define DIMD 33
#define H_ORG 2160
#define W_ORG 3840
#define HW (H_ORG * W_ORG)          // 8294400
#define LUTN (DIMD * DIMD * DIMD)   // 35937
#define NPIX 65536                  // 256*256 small image
#define NFEAT 10
#define NBLK_FEAT 256
#define NPVAL (3 * 5 * 1089)        // 16335

// ---- device scratch (no allocations allowed) ----
__device__ float    g_partials[NBLK_FEAT * NFEAT];
__device__ float    g_P[NPVAL];          // P[ch][s][q]
__device__ unsigned g_lutS32[LUTN];      // per-cell: {m0,m1,m2, E} (bias-128 int8 + pow2 exp)

// ============================================================
// Kernel A: gather features, block-reduce partial sums (deterministic)
// ============================================================
__global__ void feat_kernel(const int* __restrict__ msb, const int* __restrict__ lsb,
                            const float* __restrict__ fm, const float* __restrict__ fl) {
    int pid = blockIdx.x * 256 + threadIdx.x;

    int imr = msb[pid], img = msb[pid + NPIX], imb = msb[pid + 2 * NPIX];
    int ilr = lsb[pid], ilg = lsb[pid + NPIX], ilb = lsb[pid + 2 * NPIX];
    long imx = (long)(imr * 4096 + img * 256 + imb * 16) * NFEAT;
    long ilx = (long)(ilr * 4096 + ilg * 256 + ilb * 16) * NFEAT;

    const float4* fm4 = (const float4*)(fm + imx);
    const float4* fl4 = (const float4*)(fl + ilx);
    float4 a0 = __ldg(&fm4[0]), a1 = __ldg(&fm4[1]);
    float2 a2 = __ldg((const float2*)(fm + imx + 8));
    float4 b0 = __ldg(&fl4[0]), b1 = __ldg(&fl4[1]);
    float2 b2 = __ldg((const float2*)(fl + ilx + 8));

    float acc[NFEAT];
    acc[0] = a0.x + b0.x; acc[1] = a0.y + b0.y;
    acc[2] = a0.z + b0.z; acc[3] = a0.w + b0.w;
    acc[4] = a1.x + b1.x; acc[5] = a1.y + b1.y;
    acc[6] = a1.z + b1.z; acc[7] = a1.w + b1.w;
    acc[8] = a2.x + b2.x; acc[9] = a2.y + b2.y;

#pragma unroll
    for (int f = 0; f < NFEAT; f++) {
#pragma unroll
        for (int o = 16; o > 0; o >>= 1)
            acc[f] += __shfl_down_sync(0xffffffffu, acc[f], o);
    }

    __shared__ float sw[8][NFEAT];
    int warp = threadIdx.x >> 5, lane = threadIdx.x & 31;
    if (lane == 0) {
#pragma unroll
        for (int f = 0; f < NFEAT; f++) sw[warp][f] = acc[f];
    }
    __syncthreads();
    if (threadIdx.x == 0) {
#pragma unroll
        for (int f = 0; f < NFEAT; f++) {
            float s = 0.f;
#pragma unroll
            for (int w = 0; w < 8; w++) s += sw[w][f];
            g_partials[blockIdx.x * NFEAT + f] = s;
        }
    }
}

// ============================================================
// Kernel B: fused bweights + P. Each block redundantly computes
// pooled -> mid -> weights -> Q (deterministic), then its P chunk.
// ============================================================
__global__ void bwp_kernel(const float* __restrict__ lut_cat,
                           const float* __restrict__ luts,
                           const float* __restrict__ w_layers) {
    __shared__ int   smid[NFEAT];
    __shared__ float swt[NFEAT];
    __shared__ float sQ[150];
    int t = threadIdx.x;

    if (t < NFEAT) {
        float s = 0.f;
        for (int b = 0; b < NBLK_FEAT; b++) s += g_partials[b * NFEAT + t];
        float pooled = s * (1.0f / (float)NPIX);
        float p = rintf(pooled * 2.0f) * 0.5f;      // round half-even like jnp.round
        p = fminf(fmaxf(p, -16.0f), 15.5f);
        smid[t] = (int)(p * 2.0f) + 32;
    }
    __syncthreads();
    if (t < NFEAT) {
        float w = 0.f;
#pragma unroll
        for (int i = 0; i < 5; i++) {
            int index = smid[2 * i] * 64 + smid[2 * i + 1];
            w += (lut_cat[(i * 4096 + index) * NFEAT + t] - 32.0f) * 0.25f;
        }
        swt[t] = w;
    }
    __syncthreads();
    if (t < 150) {
        int ch = t / 50, s = (t / 10) % 5, w = t % 10;
        float q = 0.f;
#pragma unroll
        for (int n = 0; n < NFEAT; n++)
            q += swt[n] * luts[(s * 30 + 3 * n + ch) * NFEAT + w];
        sQ[t] = q;
    }
    __syncthreads();

    int idx = blockIdx.x * 256 + t;
    if (idx >= NPVAL) return;
    int chs = idx / 1089;
    int q   = idx % 1089;
    float p = 0.f;
#pragma unroll
    for (int w = 0; w < 10; w++)
        p += sQ[chs * 10 + w] * __ldg(&w_layers[w * 1089 + q]);
    g_P[idx] = p;
}

// ============================================================
// Kernel B2: final fp32 LUT -> d3lut output + per-cell int8/pow2 pack
// cell word: byte0..2 = round(val/scale)+128, byte3 = E (scale = 2^(E-127))
// scale chosen so cellmax/scale in [64,128)
// ============================================================
__global__ void lut_final_kernel(const float* __restrict__ s_layers,
                                 float* __restrict__ out_lut) {
    __shared__ float s_sl[DIMD * 5];
    if (threadIdx.x < DIMD * 5) s_sl[threadIdx.x] = s_layers[threadIdx.x];
    __syncthreads();

    int v = blockIdx.x * 256 + threadIdx.x;
    if (v >= LUTN) return;
    int b = v / 1089;
    int g = (v / 33) % 33;
    int r = v % 33;
    int qr = b * 33 + g, qg = b * 33 + r, qb = g * 33 + r;
    float Lr = 0.f, Lg = 0.f, Lb = 0.f;
#pragma unroll
    for (int s = 0; s < 5; s++) {
        Lr += s_sl[r * 5 + s] * g_P[(0 * 5 + s) * 1089 + qr];
        Lg += s_sl[g * 5 + s] * g_P[(1 * 5 + s) * 1089 + qg];
        Lb += s_sl[b * 5 + s] * g_P[(2 * 5 + s) * 1089 + qb];
    }
    out_lut[v]            = Lr;
    out_lut[LUTN + v]     = Lg;
    out_lut[2 * LUTN + v] = Lb;

    float cellmax = fmaxf(fmaxf(fabsf(Lr), fabsf(Lg)), fmaxf(fabsf(Lb), 1e-20f));
    unsigned eu = (__float_as_uint(cellmax) >> 23) & 0xFF;   // floor exponent (biased)
    unsigned E  = eu - 6;                                    // scale = 2^(e-6) -> max/scale in [64,128)
    float inv   = __uint_as_float((254u - E) << 23);         // exact 1/scale (pow2)

    int m0 = min((int)rintf(Lr * inv), 127) + 128;
    int m1 = min((int)rintf(Lg * inv), 127) + 128;
    int m2 = min((int)rintf(Lb * inv), 127) + 128;
    g_lutS32[v] = (unsigned)m0 | ((unsigned)m1 << 8) | ((unsigned)m2 << 16) | (E << 24);
}

// ============================================================
// Kernel C: persistent trilinear apply; whole LUT in shared memory
// ============================================================
#define APPLY_BLOCKS 148
#define APPLY_THREADS 1024
#define NG (HW / 4)   // 2073600 float4 pixel-groups

__device__ __forceinline__ void corner_acc(unsigned u, float w,
                                           float& S1r, float& S1g, float& S1b, float& S2) {
    unsigned h01 = __byte_perm(u, 0x64646464u, 0x4140);  // halves: 1024+m0, 1024+m1
    unsigned h2  = __byte_perm(u, 0x64646464u, 0x4442);  // low half: 1024+m2
    float s  = __uint_as_float((u & 0xFF000000u) >> 1);  // 2^(E-127)
    float ws = w * s;
    float2 f01 = __half22float2(*(__half2*)&h01);
    float  f2  = __half2float(*(__half*)&h2);
    S1r = fmaf(ws, f01.x, S1r);
    S1g = fmaf(ws, f01.y, S1g);
    S1b = fmaf(ws, f2,   S1b);
    S2 += ws;
}

__global__ void __launch_bounds__(APPLY_THREADS, 1)
apply_kernel(const float* __restrict__ img, float* __restrict__ out) {
    extern __shared__ unsigned s_lut[];

    // cooperative LUT load (coalesced)
    for (int i = threadIdx.x; i < LUTN; i += APPLY_THREADS)
        s_lut[i] = g_lutS32[i];
    __syncthreads();

    const float4* R = (const float4*)(img);
    const float4* G = (const float4*)(img + HW);
    const float4* B = (const float4*)(img + 2 * HW);
    float4* OR = (float4*)(out);
    float4* OG = (float4*)(out + HW);
    float4* OB = (float4*)(out + 2 * HW);

    const float inv_binsize = (float)((DIMD - 1) / 1.000001);

    for (int i = blockIdx.x * APPLY_THREADS + threadIdx.x; i < NG;
         i += APPLY_BLOCKS * APPLY_THREADS) {
        float4 r4 = __ldg(&R[i]), g4 = __ldg(&G[i]), b4 = __ldg(&B[i]);

        float rr[4] = {r4.x, r4.y, r4.z, r4.w};
        float gg[4] = {g4.x, g4.y, g4.z, g4.w};
        float bb[4] = {b4.x, b4.y, b4.z, b4.w};
        float ro[4], go[4], bo[4];

#pragma unroll
        for (int k = 0; k < 4; k++) {
            float rf = rr[k] * inv_binsize;
            float gf = gg[k] * inv_binsize;
            float bf = bb[k] * inv_binsize;
            float rfl = floorf(rf), gfl = floorf(gf), bfl = floorf(bf);
            int rid = min(max((int)rfl, 0), DIMD - 2);
            int gid = min(max((int)gfl, 0), DIMD - 2);
            int bid = min(max((int)bfl, 0), DIMD - 2);
            float rd = rf - rfl, gd = gf - gfl, bd = bf - bfl;

            int base = (bid * 33 + gid) * 33 + rid;

            float r1g0 = rd * (1.0f - gd);
            float r0g0 = (1.0f - gd) - r1g0;   // (1-rd)(1-gd)
            float r1g1 = rd * gd;
            float r0g1 = gd - r1g1;            // (1-rd)gd

            // plane bid
            float S1r = 0.f, S1g = 0.f, S1b = 0.f, S2 = 0.f;
            corner_acc(s_lut[base],        r0g0, S1r, S1g, S1b, S2);
            corner_acc(s_lut[base + 1],    r1g0, S1r, S1g, S1b, S2);
            corner_acc(s_lut[base + 33],   r0g1, S1r, S1g, S1b, S2);
            corner_acc(s_lut[base + 34],   r1g1, S1r, S1g, S1b, S2);
            float p0r = fmaf(-1152.0f, S2, S1r);
            float p0g = fmaf(-1152.0f, S2, S1g);
            float p0b = fmaf(-1152.0f, S2, S1b);

            // plane bid+1
            float T1r = 0.f, T1g = 0.f, T1b = 0.f, T2 = 0.f;
            corner_acc(s_lut[base + 1089], r0g0, T1r, T1g, T1b, T2);
            corner_acc(s_lut[base + 1090], r1g0, T1r, T1g, T1b, T2);
            corner_acc(s_lut[base + 1122], r0g1, T1r, T1g, T1b, T2);
            corner_acc(s_lut[base + 1123], r1g1, T1r, T1g, T1b, T2);
            float p1r = fmaf(-1152.0f, T2, T1r);
            float p1g = fmaf(-1152.0f, T2, T1g);
            float p1b = fmaf(-1152.0f, T2, T1b);

            ro[k] = fmaf(bd, p1r - p0r, p0r) + rr[k];
            go[k] = fmaf(bd, p1g - p0g, p0g) + gg[k];
            bo[k] = fmaf(bd, p1b - p0b, p0b) + bb[k];
        }

        OR[i] = make_float4(ro[0], ro[1], ro[2], ro[3]);
        OG[i] = make_float4(go[0], go[1], go[2], go[3]);
        OB[i] = make_float4(bo[0], bo[1], bo[2], bo[3]);
    }
}

// ============================================================
extern "C" void kernel_launch(void* const* d_in, const int* in_sizes, int n_in,
                              void* d_out, int out_size) {
    const int*   msb      = (const int*)d_in[0];
    const int*   lsb      = (const int*)d_in[1];
    const float* img      = (const float*)d_in[2];
    const float* fm       = (const float*)d_in[3];
    const float* fl       = (const float*)d_in[4];
    const float* lut_cat  = (const float*)d_in[5];
    const float* s_layers = (const float*)d_in[6];
    const float* w_layers = (const float*)d_in[7];
    const float* luts     = (const float*)d_in[8];
    float* out = (float*)d_out;

    const int smem_bytes = LUTN * 4;   // 143748
    cudaFuncSetAttribute(apply_kernel, cudaFuncAttributeMaxDynamicSharedMemorySize,
                         smem_bytes);

    feat_kernel<<<NBLK_FEAT, 256>>>(msb, lsb, fm, fl);
    bwp_kernel<<<(NPVAL + 255) / 256, 256>>>(lut_cat, luts, w_layers);
    lut_final_kernel<<<(LUTN + 255) / 256, 256>>>(s_layers, out + 3 * HW);
    apply_kernel<<<APPLY_BLOCKS, APPLY_THREADS, smem_bytes>>>(img, out);
}